// round 12
// baseline (speedup 1.0000x reference)
#include <cuda_runtime.h>
#include <cstdint>

#define THREADS 128

// ---- dynamic smem byte offsets ----
#define SB_B    0                 // Bpack u32 [128 k2][33] = 16896 B
#define SB_A    16896             // 2 x (256 rows x 80 B)  = 40960 B
#define SB_REI  16896             // overlay on A after GEMM (12288 B)
#define SB_CST  57856             // S 3072 + EI 512 + BI 64
#define SB_AUG  61504             // 8 x 272 floats = 8704 B
#define SMEM_BYTES 70208

// ---------- helpers ----------
__device__ __forceinline__ uint32_t smem_u32(const void* p) {
    uint32_t a;
    asm("{ .reg .u64 t; cvta.to.shared.u64 t, %1; cvt.u32.u64 %0, t; }" : "=r"(a) : "l"(p));
    return a;
}
__device__ __forceinline__ unsigned long long pk2(float lo, float hi) {
    unsigned long long r;
    asm("mov.b64 %0, {%1, %2};" : "=l"(r) : "f"(lo), "f"(hi));
    return r;
}
__device__ __forceinline__ void upk2(unsigned long long v, float& lo, float& hi) {
    asm("mov.b64 {%0, %1}, %2;" : "=f"(lo), "=f"(hi) : "l"(v));
}
__device__ __forceinline__ void ffma2(unsigned long long& acc, unsigned long long a, unsigned long long b) {
    asm("fma.rn.f32x2 %0, %1, %2, %0;" : "+l"(acc) : "l"(a), "l"(b));
}
__device__ __forceinline__ float sqrt_ap(float x){ float r; asm("sqrt.approx.f32 %0, %1;" : "=f"(r) : "f"(x)); return r; }
__device__ __forceinline__ float rcp_ap (float x){ float r; asm("rcp.approx.f32 %0, %1;"  : "=f"(r) : "f"(x)); return r; }

__device__ __forceinline__ void mma16816(float* d, uint32_t a0, uint32_t a1, uint32_t a2, uint32_t a3,
                                         uint32_t b0, uint32_t b1) {
    asm volatile(
        "mma.sync.aligned.m16n8k16.row.col.f32.bf16.bf16.f32 "
        "{%0,%1,%2,%3}, {%4,%5,%6,%7}, {%8,%9}, {%0,%1,%2,%3};"
        : "+f"(d[0]), "+f"(d[1]), "+f"(d[2]), "+f"(d[3])
        : "r"(a0), "r"(a1), "r"(a2), "r"(a3), "r"(b0), "r"(b1));
}
__device__ __forceinline__ void ldsm4(uint32_t& a0, uint32_t& a1, uint32_t& a2, uint32_t& a3, uint32_t addr) {
    asm volatile("ldmatrix.sync.aligned.m8n8.x4.shared.b16 {%0,%1,%2,%3}, [%4];"
                 : "=r"(a0), "=r"(a1), "=r"(a2), "=r"(a3) : "r"(addr));
}

__global__ __launch_bounds__(THREADS, 3)
void ocae9(const float* __restrict__ eq,  const float* __restrict__ rei,
           const float* __restrict__ Wg,  const float* __restrict__ bias,
           const float* __restrict__ envdim, const float* __restrict__ envion,
           float* __restrict__ out)
{
    extern __shared__ __align__(16) unsigned char smem[];
    const uint32_t sb = smem_u32(smem);
    uint32_t* BPW = (uint32_t*)(smem + SB_B);
    float* Ssh = (float*)(smem + SB_CST);
    float* EIs = (float*)(smem + SB_CST + 3072);
    float* BIs = (float*)(smem + SB_CST + 3584);
    float* AUG = (float*)(smem + SB_AUG);

    const int tid  = threadIdx.x;
    const int wid  = tid >> 5;
    const int lane = tid & 31;
    const int s    = blockIdx.x & 1;
    const int b0   = (blockIdx.x >> 1) * 8;   // 8 batch-spins = 128 eq rows

    // -------- stage Bpack: word k2 holds {bf16 B[2k2][n] lo, B[2k2+1][n] hi}; cols n<16 = Whi, n>=16 = Wlo --------
    #pragma unroll
    for (int u = 0; u < 32; u++) {
        int idx = tid + 128 * u;              // 0..4095
        float w = __ldg(Wg + s * 4096 + idx);
        int k = idx >> 4, o = idx & 15;
        unsigned short hb; asm("cvt.rn.bf16.f32 %0, %1;" : "=h"(hb) : "f"(w));
        float hf = __uint_as_float(((uint32_t)hb) << 16);
        float lw = w - hf;
        unsigned short lb; asm("cvt.rn.bf16.f32 %0, %1;" : "=h"(lb) : "f"(lw));
        int base = ((k >> 1) * 33) * 4 + (k & 1) * 2;
        *(unsigned short*)(smem + SB_B + base + o * 4)        = hb;
        *(unsigned short*)(smem + SB_B + base + (o + 16) * 4) = lb;
    }

    // -------- stage env constants --------
    {
        EIs[tid] = envion[s * 128 + tid];
        int ii = tid >> 4, oo = tid & 15;
        const float* A = envdim + s * 1152 + ii * 144 + oo * 9;
        float a00=A[0],a01=A[1],a02=A[2], a10=A[3],a11=A[4],a12=A[5], a20=A[6],a21=A[7],a22=A[8];
        float s00 = a00*a00 + a10*a10 + a20*a20;
        float s11 = a01*a01 + a11*a11 + a21*a21;
        float s22 = a02*a02 + a12*a12 + a22*a22;
        float s01 = 2.f*(a00*a01 + a10*a11 + a20*a21);
        float s02 = 2.f*(a00*a02 + a10*a12 + a20*a22);
        float s12 = 2.f*(a01*a02 + a11*a12 + a21*a22);
        float* dst = Ssh + (ii*8 + (oo>>1))*12 + (oo&1);
        dst[0]=s00; dst[2]=s11; dst[4]=s22; dst[6]=s01; dst[8]=s02; dst[10]=s12;
        if (tid < 16) BIs[tid] = bias[s*16 + tid];
    }

    // -------- A staging geometry: thread = (rbase = tid>>3, c = tid&7); rows rbase+16j --------
    const int c  = tid & 7;
    const int rb = tid >> 3;                  // 0..15
    const float4* gp[8];
    #pragma unroll
    for (int j = 0; j < 8; j++)
        gp[j] = (const float4*)(eq + ((size_t)(b0 + j) * 32 + s * 16 + rb) * 256) + c;
    // smem store offsets: hi row r, lo row r+128, bytes r*80 + c*8

    float4 pre[8];
    #pragma unroll
    for (int j = 0; j < 8; j++) pre[j] = __ldg(gp[j]);          // slice 0

    // store slice 0 -> buf0 (convert to bf16 hi/lo)
    #pragma unroll
    for (int j = 0; j < 8; j++) {
        float4 x4 = pre[j];
        uint32_t h01, h23;
        asm("cvt.rn.bf16x2.f32 %0, %1, %2;" : "=r"(h01) : "f"(x4.y), "f"(x4.x));
        asm("cvt.rn.bf16x2.f32 %0, %1, %2;" : "=r"(h23) : "f"(x4.w), "f"(x4.z));
        float f0 = __uint_as_float(h01 << 16), f1 = __uint_as_float(h01 & 0xFFFF0000u);
        float f2 = __uint_as_float(h23 << 16), f3 = __uint_as_float(h23 & 0xFFFF0000u);
        uint32_t l01, l23;
        asm("cvt.rn.bf16x2.f32 %0, %1, %2;" : "=r"(l01) : "f"(x4.y - f1), "f"(x4.x - f0));
        asm("cvt.rn.bf16x2.f32 %0, %1, %2;" : "=r"(l23) : "f"(x4.w - f3), "f"(x4.z - f2));
        int r = rb + 16 * j;
        uint2 hv; hv.x = h01; hv.y = h23;
        uint2 lv; lv.x = l01; lv.y = l23;
        *(uint2*)(smem + SB_A + r * 80 + c * 8)          = hv;
        *(uint2*)(smem + SB_A + (r + 128) * 80 + c * 8)  = lv;
    }
    #pragma unroll
    for (int j = 0; j < 8; j++) pre[j] = __ldg(gp[j] + 8);      // slice 1
    __syncthreads();                                            // buf0 + consts ready

    // -------- fragment geometry --------
    const int g  = lane >> 2;
    const int tg = lane & 3;
    const int lofs = ((lane & 7) + ((lane >> 3) & 1) * 8) * 80 + ((lane >> 4) & 1) * 16;
    int tb[4];
    tb[0] = (32*wid    ) * 80 + lofs;
    tb[1] = (32*wid+16 ) * 80 + lofs;
    tb[2] = (128+32*wid    ) * 80 + lofs;
    tb[3] = (128+32*wid+16 ) * 80 + lofs;

    float acc[4][4][4];
    #pragma unroll
    for (int a = 0; a < 4; a++)
        #pragma unroll
        for (int b = 0; b < 4; b++)
            #pragma unroll
            for (int j2 = 0; j2 < 4; j2++) acc[a][b][j2] = 0.f;

    // -------- GEMM: 8 k32 slices, double-buffered --------
    #pragma unroll 1
    for (int sl = 0; sl < 8; sl++) {
        if (sl < 7) {
            unsigned char* bb = smem + SB_A + ((sl + 1) & 1) * 20480;
            #pragma unroll
            for (int j = 0; j < 8; j++) {
                float4 x4 = pre[j];
                uint32_t h01, h23;
                asm("cvt.rn.bf16x2.f32 %0, %1, %2;" : "=r"(h01) : "f"(x4.y), "f"(x4.x));
                asm("cvt.rn.bf16x2.f32 %0, %1, %2;" : "=r"(h23) : "f"(x4.w), "f"(x4.z));
                float f0 = __uint_as_float(h01 << 16), f1 = __uint_as_float(h01 & 0xFFFF0000u);
                float f2 = __uint_as_float(h23 << 16), f3 = __uint_as_float(h23 & 0xFFFF0000u);
                uint32_t l01, l23;
                asm("cvt.rn.bf16x2.f32 %0, %1, %2;" : "=r"(l01) : "f"(x4.y - f1), "f"(x4.x - f0));
                asm("cvt.rn.bf16x2.f32 %0, %1, %2;" : "=r"(l23) : "f"(x4.w - f3), "f"(x4.z - f2));
                int r = rb + 16 * j;
                uint2 hv; hv.x = h01; hv.y = h23;
                uint2 lv; lv.x = l01; lv.y = l23;
                *(uint2*)(bb + r * 80 + c * 8)         = hv;
                *(uint2*)(bb + (r + 128) * 80 + c * 8) = lv;
            }
            if (sl < 6) {
                #pragma unroll
                for (int j = 0; j < 8; j++) pre[j] = __ldg(gp[j] + (sl + 2) * 8);
            }
        }

        const uint32_t abase = sb + SB_A + (sl & 1) * 20480;
        uint32_t breg[2][4][2];
        #pragma unroll
        for (int ks = 0; ks < 2; ks++)
            #pragma unroll
            for (int nt = 0; nt < 4; nt++) {
                int k2 = sl * 16 + ks * 8 + tg;
                breg[ks][nt][0] = BPW[k2 * 33 + nt * 8 + g];
                breg[ks][nt][1] = BPW[(k2 + 4) * 33 + nt * 8 + g];
            }
        #pragma unroll
        for (int ks = 0; ks < 2; ks++) {
            #pragma unroll
            for (int mt = 0; mt < 4; mt++) {
                uint32_t a0, a1, a2, a3;
                ldsm4(a0, a1, a2, a3, abase + tb[mt] + ks * 32);
                #pragma unroll
                for (int nt = 0; nt < 4; nt++)
                    mma16816(acc[mt][nt], a0, a1, a2, a3, breg[ks][nt][0], breg[ks][nt][1]);
            }
        }
        __syncthreads();
    }

    // -------- stage rei into REI (overlays A buf0) --------
    #pragma unroll
    for (int u = 0; u < 6; u++) {
        int f = tid + 128 * u;        // 0..767
        int rw = f / 6, q = f - rw * 6;
        size_t grow = ((size_t)(b0 + (rw >> 4))) * 32 + s * 16 + (rw & 15);
        *(float4*)(smem + SB_REI + (rw * 24 + q * 4) * 4) = __ldg((const float4*)rei + grow * 6 + q);
    }
    __syncthreads();

    // -------- fold quadrants: y[mt][nt][j] (+bias) --------
    float y[2][2][4];
    #pragma unroll
    for (int mt = 0; mt < 2; mt++)
        #pragma unroll
        for (int nt = 0; nt < 2; nt++)
            #pragma unroll
            for (int j = 0; j < 4; j++)
                y[mt][nt][j] = acc[mt][nt][j] + acc[mt][nt+2][j] + acc[mt+2][nt][j] + acc[mt+2][nt+2][j]
                             + BIs[8*nt + 2*tg + (j & 1)];

    // -------- env + M (4 rows per thread: (mt, rh); 2 o-pairs per row) --------
    #pragma unroll 1
    for (int mt = 0; mt < 2; mt++) {
        #pragma unroll 1
        for (int rh = 0; rh < 2; rh++) {
            const int n = 8 * rh + g;               // row within matrix
            const int mtx = 2 * wid + mt;           // local matrix
            float rv[24];
            {
                const float* rp = (const float*)(smem + SB_REI) + (mtx * 16 + n) * 24;
                #pragma unroll
                for (int q = 0; q < 6; q++) *(float4*)(rv + q * 4) = *(const float4*)(rp + q * 4);
            }
            unsigned long long ev[2] = {0ull, 0ull};
            #pragma unroll
            for (int i = 0; i < 8; i++) {
                float r0 = rv[i*3], r1 = rv[i*3+1], r2 = rv[i*3+2];
                unsigned long long p00 = pk2(r0*r0, r0*r0);
                unsigned long long p11 = pk2(r1*r1, r1*r1);
                unsigned long long p22 = pk2(r2*r2, r2*r2);
                unsigned long long p01 = pk2(r0*r1, r0*r1);
                unsigned long long p02 = pk2(r0*r2, r0*r2);
                unsigned long long p12 = pk2(r1*r2, r1*r2);
                #pragma unroll
                for (int nt = 0; nt < 2; nt++) {
                    int op = 4 * nt + tg;
                    const unsigned long long* Sp = (const unsigned long long*)(Ssh + (i*8 + op) * 12);
                    unsigned long long q = 0ull;
                    ffma2(q, Sp[0], p00); ffma2(q, Sp[1], p11); ffma2(q, Sp[2], p22);
                    ffma2(q, Sp[3], p01); ffma2(q, Sp[4], p02); ffma2(q, Sp[5], p12);
                    float q0, q1; upk2(q, q0, q1);
                    float e0 = __expf(-sqrt_ap(fmaxf(q0, 0.f)));
                    float e1 = __expf(-sqrt_ap(fmaxf(q1, 0.f)));
                    ffma2(ev[nt], pk2(e0, e1), *((const unsigned long long*)EIs + i*8 + op));
                }
            }
            #pragma unroll
            for (int nt = 0; nt < 2; nt++) {
                float e0, e1; upk2(ev[nt], e0, e1);
                int c0 = 8*nt + 2*tg;
                AUG[mtx*272 + c0*17 + n]     = y[mt][nt][2*rh]   * e0;   // (M^T)[o][n]
                AUG[mtx*272 + (c0+1)*17 + n] = y[mt][nt][2*rh+1] * e1;
            }
        }
    }
    __syncwarp();   // warp wid owns matrices 2wid, 2wid+1 end-to-end

    // -------- cofactors: register LU, 2 x 16-lane segments per warp --------
    const unsigned FULL = 0xffffffffu;
    const int seg = lane >> 4;
    const int o   = lane & 15;
    const int m   = 2 * wid + seg;

    float a[17];
    {
        const float* Ma = AUG + m * 272 + o * 17;
        #pragma unroll
        for (int j = 0; j < 16; j++) a[j] = Ma[j];
        a[16] = (o == 0) ? 1.f : 0.f;
    }
    float det = 1.f;

    #pragma unroll
    for (int k = 0; k < 16; k++) {
        float v = (o >= k) ? fabsf(a[k]) : -1.f;
        int   p = o;
        #pragma unroll
        for (int off = 8; off; off >>= 1) {
            float ov = __shfl_xor_sync(FULL, v, off, 16);
            int   oq = __shfl_xor_sync(FULL, p, off, 16);
            if (ov > v || (ov == v && oq < p)) { v = ov; p = oq; }
        }
        float pvk = __shfl_sync(FULL, a[k], p, 16);
        float kvk = __shfl_sync(FULL, a[k], k, 16);
        if (o == k) a[k] = pvk; else if (o == p) a[k] = kvk;
        det = (p != k) ? -det : det;
        det *= pvk;
        float mlt = (o > k) ? a[k] * rcp_ap(pvk) : 0.f;
        #pragma unroll
        for (int j = k + 1; j < 17; j++) {
            float pv = __shfl_sync(FULL, a[j], p, 16);
            float kv = __shfl_sync(FULL, a[j], k, 16);
            if (o == k) a[j] = pv; else if (o == p) a[j] = kv;
            a[j] -= mlt * pv;
        }
    }

    float z = 0.f, rhs = a[16];
    #pragma unroll
    for (int k = 15; k >= 0; k--) {
        float num = __shfl_sync(FULL, rhs,  k, 16);
        float den = __shfl_sync(FULL, a[k], k, 16);
        float xk = num * rcp_ap(den);
        if (o == k) z = xk;
        rhs -= a[k] * xk;
    }

    float c0 = AUG[m * 272 + o];   // M[o][0]
    out[((size_t)(b0 + m) * 2 + s) * 16 + o] = c0 * det * z;
}

extern "C" void kernel_launch(void* const* d_in, const int* in_sizes, int n_in,
                              void* d_out, int out_size)
{
    const float* eq  = (const float*)d_in[0];
    const float* rei = (const float*)d_in[1];
    const float* W   = (const float*)d_in[2];
    const float* b   = (const float*)d_in[3];
    const float* ed  = (const float*)d_in[4];
    const float* ei  = (const float*)d_in[5];
    float* out = (float*)d_out;

    int B = in_sizes[0] / (32 * 256);        // 4096
    cudaFuncSetAttribute(ocae9, cudaFuncAttributeMaxDynamicSharedMemorySize, SMEM_BYTES);
    dim3 grid((B / 8) * 2);                  // 1024 blocks
    ocae9<<<grid, THREADS, SMEM_BYTES>>>(eq, rei, W, b, ed, ei, out);
}

// round 13
// speedup vs baseline: 1.4880x; 1.4880x over previous
#include <cuda_runtime.h>
#include <cstdint>

#define THREADS 128

// ---- dynamic smem byte offsets ----
#define SB_B    0         // Bpack u32 [128 k2][40] = 20480 B (stride 40: conflict-free frag loads)
#define SB_A    20480     // 2 x 16384 B  A slice buffers (256 rows x 64 B, swizzled)
#define SB_REI  20480     // overlay on A after GEMM (12288 B)
#define SB_AUG  32768     // overlay on A: 8 x 272 floats = 8704 B
#define SB_CST  53248     // S 3072 | EI 512 | BI 64
#define SMEM_BYTES 56896

// ---------- helpers ----------
__device__ __forceinline__ uint32_t smem_u32(const void* p) {
    uint32_t a;
    asm("{ .reg .u64 t; cvta.to.shared.u64 t, %1; cvt.u32.u64 %0, t; }" : "=r"(a) : "l"(p));
    return a;
}
__device__ __forceinline__ unsigned long long pk2(float lo, float hi) {
    unsigned long long r;
    asm("mov.b64 %0, {%1, %2};" : "=l"(r) : "f"(lo), "f"(hi));
    return r;
}
__device__ __forceinline__ void upk2(unsigned long long v, float& lo, float& hi) {
    asm("mov.b64 {%0, %1}, %2;" : "=f"(lo), "=f"(hi) : "l"(v));
}
__device__ __forceinline__ void ffma2(unsigned long long& acc, unsigned long long a, unsigned long long b) {
    asm("fma.rn.f32x2 %0, %1, %2, %0;" : "+l"(acc) : "l"(a), "l"(b));
}
__device__ __forceinline__ float sqrt_ap(float x){ float r; asm("sqrt.approx.f32 %0, %1;" : "=f"(r) : "f"(x)); return r; }
__device__ __forceinline__ float rcp_ap (float x){ float r; asm("rcp.approx.f32 %0, %1;"  : "=f"(r) : "f"(x)); return r; }

__device__ __forceinline__ void mma16816(float* d, uint32_t a0, uint32_t a1, uint32_t a2, uint32_t a3,
                                         uint32_t b0, uint32_t b1) {
    asm volatile(
        "mma.sync.aligned.m16n8k16.row.col.f32.bf16.bf16.f32 "
        "{%0,%1,%2,%3}, {%4,%5,%6,%7}, {%8,%9}, {%0,%1,%2,%3};"
        : "+f"(d[0]), "+f"(d[1]), "+f"(d[2]), "+f"(d[3])
        : "r"(a0), "r"(a1), "r"(a2), "r"(a3), "r"(b0), "r"(b1));
}
__device__ __forceinline__ void ldsm4(uint32_t& a0, uint32_t& a1, uint32_t& a2, uint32_t& a3, uint32_t addr) {
    asm volatile("ldmatrix.sync.aligned.m8n8.x4.shared.b16 {%0,%1,%2,%3}, [%4];"
                 : "=r"(a0), "=r"(a1), "=r"(a2), "=r"(a3) : "r"(addr));
}

// convert float4 -> bf16 hi uint2 + lo uint2
__device__ __forceinline__ void cvt_hilo(float4 x4, uint2& hv, uint2& lv) {
    uint32_t h01, h23;
    asm("cvt.rn.bf16x2.f32 %0, %1, %2;" : "=r"(h01) : "f"(x4.y), "f"(x4.x));
    asm("cvt.rn.bf16x2.f32 %0, %1, %2;" : "=r"(h23) : "f"(x4.w), "f"(x4.z));
    float f0 = __uint_as_float(h01 << 16), f1 = __uint_as_float(h01 & 0xFFFF0000u);
    float f2 = __uint_as_float(h23 << 16), f3 = __uint_as_float(h23 & 0xFFFF0000u);
    uint32_t l01, l23;
    asm("cvt.rn.bf16x2.f32 %0, %1, %2;" : "=r"(l01) : "f"(x4.y - f1), "f"(x4.x - f0));
    asm("cvt.rn.bf16x2.f32 %0, %1, %2;" : "=r"(l23) : "f"(x4.w - f3), "f"(x4.z - f2));
    hv.x = h01; hv.y = h23; lv.x = l01; lv.y = l23;
}

__global__ __launch_bounds__(THREADS, 4)
void ocae10(const float* __restrict__ eq,  const float* __restrict__ rei,
            const float* __restrict__ Wg,  const float* __restrict__ bias,
            const float* __restrict__ envdim, const float* __restrict__ envion,
            float* __restrict__ out)
{
    extern __shared__ __align__(16) unsigned char smem[];
    const uint32_t sb = smem_u32(smem);
    uint32_t* BPW = (uint32_t*)(smem + SB_B);
    float* Ssh = (float*)(smem + SB_CST);
    float* EIs = (float*)(smem + SB_CST + 3072);
    float* BIs = (float*)(smem + SB_CST + 3584);
    float* AUG = (float*)(smem + SB_AUG);

    const int tid  = threadIdx.x;
    const int wid  = tid >> 5;
    const int lane = tid & 31;
    const int s    = blockIdx.x & 1;
    const int b0   = (blockIdx.x >> 1) * 8;   // 8 batch-spins = 128 eq rows

    // -------- stage Bpack, stride 40 words: word k2*40+n = {B[2k2][n], B[2k2+1][n]}; n<16 hi, n>=16 lo --------
    #pragma unroll
    for (int u = 0; u < 32; u++) {
        int idx = tid + 128 * u;              // 0..4095
        float w = __ldg(Wg + s * 4096 + idx);
        int k = idx >> 4, o = idx & 15;
        unsigned short hb; asm("cvt.rn.bf16.f32 %0, %1;" : "=h"(hb) : "f"(w));
        float hf = __uint_as_float(((uint32_t)hb) << 16);
        float lw = w - hf;
        unsigned short lb; asm("cvt.rn.bf16.f32 %0, %1;" : "=h"(lb) : "f"(lw));
        int base = (k >> 1) * 160 + (k & 1) * 2;
        *(unsigned short*)(smem + SB_B + base + o * 4)      = hb;
        *(unsigned short*)(smem + SB_B + base + 64 + o * 4) = lb;
    }

    // -------- stage env constants --------
    {
        EIs[tid] = envion[s * 128 + tid];
        int ii = tid >> 4, oo = tid & 15;
        const float* A = envdim + s * 1152 + ii * 144 + oo * 9;
        float a00=A[0],a01=A[1],a02=A[2], a10=A[3],a11=A[4],a12=A[5], a20=A[6],a21=A[7],a22=A[8];
        float s00 = a00*a00 + a10*a10 + a20*a20;
        float s11 = a01*a01 + a11*a11 + a21*a21;
        float s22 = a02*a02 + a12*a12 + a22*a22;
        float s01 = 2.f*(a00*a01 + a10*a11 + a20*a21);
        float s02 = 2.f*(a00*a02 + a10*a12 + a20*a22);
        float s12 = 2.f*(a01*a02 + a11*a12 + a21*a22);
        float* dst = Ssh + (ii*8 + (oo>>1))*12 + (oo&1);
        dst[0]=s00; dst[2]=s11; dst[4]=s22; dst[6]=s01; dst[8]=s02; dst[10]=s12;
        if (tid < 16) BIs[tid] = bias[s*16 + tid];
    }

    // -------- A staging geometry: thread = (rb = tid>>3, c = tid&7); rows rb+16j --------
    const int c  = tid & 7;
    const int rb = tid >> 3;                  // 0..15
    const float4* gp0 = (const float4*)(eq + ((size_t)b0 * 32 + s * 16 + rb) * 256) + c;
    // per jj: gp = gp0 + jj*2048 (batch stride 32*256 floats = 2048 float4)
    // store offset (hi): row r=16jj+rb -> r*64 + swz; swz = ((c>>1)+(rb>>1))&3 (jj drops mod 4)
    const int soH = rb * 64 + ((((c >> 1) + (rb >> 1)) & 3) << 4) + (c & 1) * 8;

    float4 pre[8];
    #pragma unroll
    for (int j = 0; j < 8; j++) pre[j] = __ldg(gp0 + j * 2048);          // slice 0

    // store slice 0 -> buf0
    #pragma unroll
    for (int j = 0; j < 8; j++) {
        uint2 hv, lv; cvt_hilo(pre[j], hv, lv);
        *(uint2*)(smem + SB_A + j * 1024 + soH)        = hv;
        *(uint2*)(smem + SB_A + j * 1024 + soH + 8192) = lv;
    }
    #pragma unroll
    for (int j = 0; j < 8; j++) pre[j] = __ldg(gp0 + j * 2048 + 8);      // slice 1
    __syncthreads();                                                     // consts + buf0 ready

    // -------- fragment geometry --------
    const int g  = lane >> 2;
    const int tg = lane & 3;
    const int ln = lane & 15;
    const int rowl  = 32 * wid + ln;                 // hi row for mt=0 (mt=1: +16)
    const int swq   = (lane >> 4) + (ln >> 1);       // + 2*ks, &3 for chunk

    float acc[2][2][4];
    #pragma unroll
    for (int a = 0; a < 2; a++)
        #pragma unroll
        for (int b = 0; b < 2; b++)
            #pragma unroll
            for (int j2 = 0; j2 < 4; j2++) acc[a][b][j2] = 0.f;

    // -------- GEMM: 8 k32 slices, double-buffered, 1 barrier/slice --------
    #pragma unroll 1
    for (int sl = 0; sl < 8; sl++) {
        if (sl < 7) {
            unsigned char* bb = smem + SB_A + ((sl + 1) & 1) * 16384;
            #pragma unroll
            for (int j = 0; j < 8; j++) {
                uint2 hv, lv; cvt_hilo(pre[j], hv, lv);
                *(uint2*)(bb + j * 1024 + soH)        = hv;
                *(uint2*)(bb + j * 1024 + soH + 8192) = lv;
            }
            if (sl < 6) {
                #pragma unroll
                for (int j = 0; j < 8; j++) pre[j] = __ldg(gp0 + j * 2048 + (sl + 2) * 8);
            }
        }

        const uint32_t abase = sb + SB_A + (sl & 1) * 16384;
        #pragma unroll
        for (int ks = 0; ks < 2; ks++) {
            int k2 = sl * 16 + ks * 8 + tg;
            uint32_t bh[2][2], bl[2][2];
            #pragma unroll
            for (int nt = 0; nt < 2; nt++) {
                bh[nt][0] = BPW[k2 * 40 + nt * 8 + g];
                bh[nt][1] = BPW[(k2 + 4) * 40 + nt * 8 + g];
                bl[nt][0] = BPW[k2 * 40 + 16 + nt * 8 + g];
                bl[nt][1] = BPW[(k2 + 4) * 40 + 16 + nt * 8 + g];
            }
            const uint32_t chunk = ((ks * 2 + swq) & 3) << 4;
            #pragma unroll
            for (int mt = 0; mt < 2; mt++) {
                uint32_t rofs = (rowl + mt * 16) * 64 + chunk;
                uint32_t h0, h1, h2, h3, l0, l1, l2, l3;
                ldsm4(h0, h1, h2, h3, abase + rofs);
                ldsm4(l0, l1, l2, l3, abase + rofs + 8192);
                #pragma unroll
                for (int nt = 0; nt < 2; nt++) {
                    mma16816(acc[mt][nt], h0, h1, h2, h3, bh[nt][0], bh[nt][1]);
                    mma16816(acc[mt][nt], h0, h1, h2, h3, bl[nt][0], bl[nt][1]);
                    mma16816(acc[mt][nt], l0, l1, l2, l3, bh[nt][0], bh[nt][1]);
                }
            }
        }
        __syncthreads();
    }

    // -------- stage rei into REI (overlays A) --------
    #pragma unroll
    for (int u = 0; u < 6; u++) {
        int f = tid + 128 * u;        // 0..767
        int rw = f / 6, q = f - rw * 6;
        size_t grow = ((size_t)(b0 + (rw >> 4))) * 32 + s * 16 + (rw & 15);
        *(float4*)(smem + SB_REI + (rw * 24 + q * 4) * 4) = __ldg((const float4*)rei + grow * 6 + q);
    }
    __syncthreads();

    // -------- y = acc + bias --------
    float y[2][2][4];
    #pragma unroll
    for (int mt = 0; mt < 2; mt++)
        #pragma unroll
        for (int nt = 0; nt < 2; nt++)
            #pragma unroll
            for (int j = 0; j < 4; j++)
                y[mt][nt][j] = acc[mt][nt][j] + BIs[8*nt + 2*tg + (j & 1)];

    // -------- env + M (4 rows per thread: (mt, rh); 2 o-pairs per row) --------
    #pragma unroll 1
    for (int mt = 0; mt < 2; mt++) {
        #pragma unroll 1
        for (int rh = 0; rh < 2; rh++) {
            const int n = 8 * rh + g;               // row within matrix
            const int mtx = 2 * wid + mt;           // local matrix
            float rv[24];
            {
                const float* rp = (const float*)(smem + SB_REI) + (mtx * 16 + n) * 24;
                #pragma unroll
                for (int q = 0; q < 6; q++) *(float4*)(rv + q * 4) = *(const float4*)(rp + q * 4);
            }
            unsigned long long ev[2] = {0ull, 0ull};
            #pragma unroll
            for (int i = 0; i < 8; i++) {
                float r0 = rv[i*3], r1 = rv[i*3+1], r2 = rv[i*3+2];
                unsigned long long p00 = pk2(r0*r0, r0*r0);
                unsigned long long p11 = pk2(r1*r1, r1*r1);
                unsigned long long p22 = pk2(r2*r2, r2*r2);
                unsigned long long p01 = pk2(r0*r1, r0*r1);
                unsigned long long p02 = pk2(r0*r2, r0*r2);
                unsigned long long p12 = pk2(r1*r2, r1*r2);
                #pragma unroll
                for (int nt = 0; nt < 2; nt++) {
                    int op = 4 * nt + tg;
                    const unsigned long long* Sp = (const unsigned long long*)(Ssh + (i*8 + op) * 12);
                    unsigned long long q = 0ull;
                    ffma2(q, Sp[0], p00); ffma2(q, Sp[1], p11); ffma2(q, Sp[2], p22);
                    ffma2(q, Sp[3], p01); ffma2(q, Sp[4], p02); ffma2(q, Sp[5], p12);
                    float q0, q1; upk2(q, q0, q1);
                    float e0 = __expf(-sqrt_ap(fmaxf(q0, 0.f)));
                    float e1 = __expf(-sqrt_ap(fmaxf(q1, 0.f)));
                    ffma2(ev[nt], pk2(e0, e1), *((const unsigned long long*)EIs + i*8 + op));
                }
            }
            #pragma unroll
            for (int nt = 0; nt < 2; nt++) {
                float e0, e1; upk2(ev[nt], e0, e1);
                int c0 = 8*nt + 2*tg;
                AUG[mtx*272 + c0*17 + n]     = y[mt][nt][2*rh]   * e0;   // (M^T)[o][n]
                AUG[mtx*272 + (c0+1)*17 + n] = y[mt][nt][2*rh+1] * e1;
            }
        }
    }
    __syncwarp();   // warp wid owns matrices 2wid, 2wid+1 end-to-end

    // -------- cofactors: register LU, 2 x 16-lane segments per warp --------
    const unsigned FULL = 0xffffffffu;
    const int seg = lane >> 4;
    const int o   = lane & 15;
    const int m   = 2 * wid + seg;

    float a[17];
    {
        const float* Ma = AUG + m * 272 + o * 17;
        #pragma unroll
        for (int j = 0; j < 16; j++) a[j] = Ma[j];
        a[16] = (o == 0) ? 1.f : 0.f;
    }
    float det = 1.f;

    #pragma unroll
    for (int k = 0; k < 16; k++) {
        float v = (o >= k) ? fabsf(a[k]) : -1.f;
        int   p = o;
        #pragma unroll
        for (int off = 8; off; off >>= 1) {
            float ov = __shfl_xor_sync(FULL, v, off, 16);
            int   oq = __shfl_xor_sync(FULL, p, off, 16);
            if (ov > v || (ov == v && oq < p)) { v = ov; p = oq; }
        }
        float pvk = __shfl_sync(FULL, a[k], p, 16);
        float kvk = __shfl_sync(FULL, a[k], k, 16);
        if (o == k) a[k] = pvk; else if (o == p) a[k] = kvk;
        det = (p != k) ? -det : det;
        det *= pvk;
        float mlt = (o > k) ? a[k] * rcp_ap(pvk) : 0.f;
        #pragma unroll
        for (int j = k + 1; j < 17; j++) {
            float pv = __shfl_sync(FULL, a[j], p, 16);
            float kv = __shfl_sync(FULL, a[j], k, 16);
            if (o == k) a[j] = pv; else if (o == p) a[j] = kv;
            a[j] -= mlt * pv;
        }
    }

    float z = 0.f, rhs = a[16];
    #pragma unroll
    for (int k = 15; k >= 0; k--) {
        float num = __shfl_sync(FULL, rhs,  k, 16);
        float den = __shfl_sync(FULL, a[k], k, 16);
        float xk = num * rcp_ap(den);
        if (o == k) z = xk;
        rhs -= a[k] * xk;
    }

    float c0v = AUG[m * 272 + o];   // M[o][0]
    out[((size_t)(b0 + m) * 2 + s) * 16 + o] = c0v * det * z;
}

extern "C" void kernel_launch(void* const* d_in, const int* in_sizes, int n_in,
                              void* d_out, int out_size)
{
    const float* eq  = (const float*)d_in[0];
    const float* rei = (const float*)d_in[1];
    const float* W   = (const float*)d_in[2];
    const float* b   = (const float*)d_in[3];
    const float* ed  = (const float*)d_in[4];
    const float* ei  = (const float*)d_in[5];
    float* out = (float*)d_out;

    int B = in_sizes[0] / (32 * 256);        // 4096
    cudaFuncSetAttribute(ocae10, cudaFuncAttributeMaxDynamicSharedMemorySize, SMEM_BYTES);
    dim3 grid((B / 8) * 2);                  // 1024 blocks
    ocae10<<<grid, THREADS, SMEM_BYTES>>>(eq, rei, W, b, ed, ei, out);
}